// round 1
// baseline (speedup 1.0000x reference)
#include <cuda_runtime.h>
#include <cuda_bf16.h>

// Problem constants
#define NN    4096
#define INF_  256
#define FF    64
#define HH    4
#define CC    256      // HH*FF
#define NEG_SLOPE 0.2f

#define JSPLIT 2
#define JHALF  (NN / JSPLIT)
#define ITILE  64
#define JT     32

// Scratch (device globals: allocation-free rule)
__device__ float g_h[NN * CC];            // 4 MB
__device__ float g_el[NN * HH];
__device__ float g_er[NN * HH];
__device__ float g_acc[JSPLIT * NN * CC]; // 8 MB partial accumulators
__device__ float g_z[JSPLIT * NN * HH];   // partial softmax denominators

// ---------------------------------------------------------------------------
// Kernel 1: h = x @ W   (4096x256 @ 256x256), 64x64 tile, 256 thr, 4x4/thread
// ---------------------------------------------------------------------------
__global__ void k_gemm_xw(const float* __restrict__ x,
                          const float* __restrict__ W) {
    __shared__ float x_s[64][17];
    __shared__ float W_s[16][64];

    const int t  = threadIdx.x;
    const int i0 = blockIdx.x * 64;
    const int n0 = blockIdx.y * 64;
    const int tcx = t & 15;        // 0..15 col-thread
    const int trx = t >> 4;        // 0..15 row-thread

    float acc[4][4];
#pragma unroll
    for (int m = 0; m < 4; m++)
#pragma unroll
        for (int n = 0; n < 4; n++) acc[m][n] = 0.f;

    for (int k0 = 0; k0 < INF_; k0 += 16) {
        // load x tile 64x16
#pragma unroll
        for (int k = 0; k < 4; k++) {
            int idx = k * 256 + t;
            int r = idx >> 4, c = idx & 15;
            x_s[r][c] = x[(i0 + r) * INF_ + k0 + c];
        }
        // load W tile 16x64
#pragma unroll
        for (int k = 0; k < 4; k++) {
            int idx = k * 256 + t;
            int r = idx >> 6, c = idx & 63;
            W_s[r][c] = W[(k0 + r) * CC + n0 + c];
        }
        __syncthreads();
#pragma unroll
        for (int kk = 0; kk < 16; kk++) {
            float a0 = x_s[trx * 4 + 0][kk];
            float a1 = x_s[trx * 4 + 1][kk];
            float a2 = x_s[trx * 4 + 2][kk];
            float a3 = x_s[trx * 4 + 3][kk];
            float4 b = *(const float4*)&W_s[kk][tcx * 4];
            acc[0][0] += a0 * b.x; acc[0][1] += a0 * b.y; acc[0][2] += a0 * b.z; acc[0][3] += a0 * b.w;
            acc[1][0] += a1 * b.x; acc[1][1] += a1 * b.y; acc[1][2] += a1 * b.z; acc[1][3] += a1 * b.w;
            acc[2][0] += a2 * b.x; acc[2][1] += a2 * b.y; acc[2][2] += a2 * b.z; acc[2][3] += a2 * b.w;
            acc[3][0] += a3 * b.x; acc[3][1] += a3 * b.y; acc[3][2] += a3 * b.z; acc[3][3] += a3 * b.w;
        }
        __syncthreads();
    }
#pragma unroll
    for (int m = 0; m < 4; m++) {
        float4 v = make_float4(acc[m][0], acc[m][1], acc[m][2], acc[m][3]);
        *(float4*)&g_h[(i0 + trx * 4 + m) * CC + n0 + tcx * 4] = v;
    }
}

// ---------------------------------------------------------------------------
// Kernel 2: el[n,h] = sum_f h[n,h,f]*a_l[f]; er likewise with a_r.
// One block per node, warp per head.
// ---------------------------------------------------------------------------
__global__ void k_elr(const float* __restrict__ a) {
    const int i    = blockIdx.x;
    const int wid  = threadIdx.x >> 5;   // head
    const int lane = threadIdx.x & 31;

    float v1 = g_h[i * CC + wid * FF + lane];
    float v2 = g_h[i * CC + wid * FF + lane + 32];
    float el = v1 * a[lane]      + v2 * a[lane + 32];
    float er = v1 * a[64 + lane] + v2 * a[96 + lane];
#pragma unroll
    for (int off = 16; off > 0; off >>= 1) {
        el += __shfl_xor_sync(0xffffffffu, el, off);
        er += __shfl_xor_sync(0xffffffffu, er, off);
    }
    if (lane == 0) {
        g_el[i * HH + wid] = el;
        g_er[i * HH + wid] = er;
    }
}

// ---------------------------------------------------------------------------
// Kernel 3: fused masked attention + weighted aggregation (partials).
// Grid: (64 i-tiles, JSPLIT). Block: 256 threads.
// Per block: 64 rows x 256 cols accumulator; per thread 8x8 register tile
// inside one head.
// ---------------------------------------------------------------------------
__global__ void __launch_bounds__(256) k_attn(const float* __restrict__ adj) {
    extern __shared__ float smem[];
    float* hs    = smem;           // [JT][256]   8192
    float* w_s   = smem + 8192;    // [JT][256]   8192
    float* adj_s = smem + 16384;   // [64][33]    2112
    float* el_s  = smem + 18496;   // [64][4]      256
    float* er_s  = smem + 18752;   // [JT][4]      128

    const int t  = threadIdx.x;
    const int i0 = blockIdx.x * ITILE;
    const int js = blockIdx.y;
    const int jbase = js * JHALF;

    // mapping for w-phase
    const int h_w = t >> 6;        // 0..3
    const int i_w = t & 63;        // 0..63
    // mapping for GEMM phase
    const int h_g = t >> 6;        // 0..3
    const int tr  = (t >> 3) & 7;  // 0..7 rows
    const int tc  = t & 7;         // 0..7 cols

    // load el for this i-tile
    el_s[t] = g_el[i0 * HH + t];
    __syncthreads();
    const float el_v = el_s[i_w * HH + h_w];

    float acc[8][8];
#pragma unroll
    for (int r = 0; r < 8; r++)
#pragma unroll
        for (int c = 0; c < 8; c++) acc[r][c] = 0.f;
    float zacc = 0.f;

    for (int jt = 0; jt < JHALF; jt += JT) {
        const int j0 = jbase + jt;
        __syncthreads();   // previous GEMM done, safe to overwrite smem

        // --- load phase ---
        // hs: JT x 256 floats, float4 vectorized
#pragma unroll
        for (int k = 0; k < 8; k++) {
            int f4 = k * 256 + t;          // 0..2047
            int jj = f4 >> 6, c4 = f4 & 63;
            *(float4*)&hs[jj * CC + c4 * 4] =
                *(const float4*)&g_h[(j0 + jj) * CC + c4 * 4];
        }
        // adj: 64 x JT, padded pitch 33
#pragma unroll
        for (int k = 0; k < 8; k++) {
            int idx = k * 256 + t;
            int r = idx >> 5, c = idx & 31;
            adj_s[r * 33 + c] = adj[(size_t)(i0 + r) * NN + j0 + c];
        }
        // er: JT x 4
        if (t < JT * HH) er_s[t] = g_er[j0 * HH + t];
        __syncthreads();

        // --- w phase: thread owns (i_w, h_w), loops over jj ---
#pragma unroll 4
        for (int jj = 0; jj < JT; jj++) {
            float s = el_v + er_s[jj * HH + h_w];
            float e = fmaxf(s, NEG_SLOPE * s);        // leaky relu
            float w = adj_s[i_w * 33 + jj] * __expf(e);
            w_s[jj * CC + h_w * 64 + i_w] = w;
            zacc += w;
        }
        __syncthreads();

        // --- GEMM phase: acc[8][8] += w[i][jj] * h[jj][c] ---
#pragma unroll 2
        for (int jj = 0; jj < JT; jj++) {
            const float* wp = &w_s[jj * CC + h_g * 64 + tr * 8];
            const float* hp = &hs[jj * CC + h_g * 64 + tc * 8];
            float4 w0 = *(const float4*)(wp);
            float4 w1 = *(const float4*)(wp + 4);
            float4 b0 = *(const float4*)(hp);
            float4 b1 = *(const float4*)(hp + 4);
            float wv[8] = {w0.x, w0.y, w0.z, w0.w, w1.x, w1.y, w1.z, w1.w};
            float bv[8] = {b0.x, b0.y, b0.z, b0.w, b1.x, b1.y, b1.z, b1.w};
#pragma unroll
            for (int r = 0; r < 8; r++)
#pragma unroll
                for (int c = 0; c < 8; c++)
                    acc[r][c] += wv[r] * bv[c];
        }
    }

    // --- epilogue: write partials ---
    float* accb = g_acc + (size_t)js * NN * CC;
#pragma unroll
    for (int r = 0; r < 8; r++) {
        int row = i0 + tr * 8 + r;
        float4 v0 = make_float4(acc[r][0], acc[r][1], acc[r][2], acc[r][3]);
        float4 v1 = make_float4(acc[r][4], acc[r][5], acc[r][6], acc[r][7]);
        *(float4*)&accb[(size_t)row * CC + h_g * 64 + tc * 8]     = v0;
        *(float4*)&accb[(size_t)row * CC + h_g * 64 + tc * 8 + 4] = v1;
    }
    g_z[(size_t)js * NN * HH + (i0 + i_w) * HH + h_w] = zacc;
}

// ---------------------------------------------------------------------------
// Kernel 4: finalize out[i][f] = (1/H) * sum_h (acc0+acc1)[i][h*64+f]/(z0+z1)[i][h]
// ---------------------------------------------------------------------------
__global__ void k_finalize(float* __restrict__ out) {
    int idx = blockIdx.x * blockDim.x + threadIdx.x;   // 0 .. N*FF-1
    int i = idx >> 6, f = idx & 63;
    float sum = 0.f;
#pragma unroll
    for (int h = 0; h < HH; h++) {
        float A = g_acc[(size_t)i * CC + h * 64 + f] +
                  g_acc[(size_t)NN * CC + (size_t)i * CC + h * 64 + f];
        float Z = g_z[i * HH + h] + g_z[NN * HH + i * HH + h];
        sum += A / Z;
    }
    out[idx] = 0.25f * sum;
}

// ---------------------------------------------------------------------------
extern "C" void kernel_launch(void* const* d_in, const int* in_sizes, int n_in,
                              void* d_out, int out_size) {
    const float* x   = (const float*)d_in[0];
    const float* adj = (const float*)d_in[1];
    const float* W   = (const float*)d_in[2];
    const float* a   = (const float*)d_in[3];
    float* out = (float*)d_out;

    static int smem_set = -1;
    const int attn_smem = 18880 * 4;
    // (cudaFuncSetAttribute is idempotent & cheap; call every time — no guards
    //  that change behavior across calls)
    cudaFuncSetAttribute(k_attn, cudaFuncAttributeMaxDynamicSharedMemorySize,
                         attn_smem);
    (void)smem_set;

    k_gemm_xw<<<dim3(NN / 64, CC / 64), 256>>>(x, W);
    k_elr<<<NN, 128>>>(a);
    k_attn<<<dim3(NN / ITILE, JSPLIT), 256, attn_smem>>>(adj);
    k_finalize<<<(NN * FF) / 256, 256>>>(out);
}

// round 2
// speedup vs baseline: 1.2058x; 1.2058x over previous
#include <cuda_runtime.h>
#include <cuda_bf16.h>

// Problem constants
#define NN    4096
#define INF_  256
#define FF    64
#define HH    4
#define CC    256      // HH*FF
#define NEG_SLOPE 0.2f

#define JSPLIT 2
#define JHALF  (NN / JSPLIT)
#define ITILE  64
#define JT     32

// Scratch (device globals: allocation-free rule)
__device__ float  g_h[NN * CC];            // 4 MB
__device__ float2 g_eL[NN * HH];           // (exp(el), exp(0.2*el))
__device__ float2 g_eR[NN * HH];           // (exp(er), exp(0.2*er))
__device__ float  g_acc[JSPLIT * NN * CC]; // 8 MB partial accumulators
__device__ float  g_z[JSPLIT * NN * HH];   // partial softmax denominators

// ---- packed f32x2 helpers (sm_103a) ----
__device__ __forceinline__ unsigned long long pk2(float lo, float hi) {
    unsigned long long r;
    asm("mov.b64 %0, {%1, %2};" : "=l"(r) : "f"(lo), "f"(hi));
    return r;
}
__device__ __forceinline__ void upk2(unsigned long long v, float& lo, float& hi) {
    asm("mov.b64 {%0, %1}, %2;" : "=f"(lo), "=f"(hi) : "l"(v));
}
#define FFMA2(d, a, b) \
    asm("fma.rn.f32x2 %0, %1, %2, %0;" : "+l"(d) : "l"(a), "l"(b))

// ---------------------------------------------------------------------------
// Kernel 1: h = x @ W   (4096x256 @ 256x256), 64x64 tile, 256 thr, 4x4/thread
// ---------------------------------------------------------------------------
__global__ void k_gemm_xw(const float* __restrict__ x,
                          const float* __restrict__ W) {
    __shared__ float x_s[64][17];
    __shared__ __align__(16) float W_s[16][64];

    const int t  = threadIdx.x;
    const int i0 = blockIdx.x * 64;
    const int n0 = blockIdx.y * 64;
    const int tcx = t & 15;        // 0..15 col-thread
    const int trx = t >> 4;        // 0..15 row-thread

    unsigned long long acc2[4][2];
#pragma unroll
    for (int m = 0; m < 4; m++) {
        acc2[m][0] = 0ull; acc2[m][1] = 0ull;
    }

    for (int k0 = 0; k0 < INF_; k0 += 16) {
#pragma unroll
        for (int k = 0; k < 4; k++) {
            int idx = k * 256 + t;
            int r = idx >> 4, c = idx & 15;
            x_s[r][c] = x[(i0 + r) * INF_ + k0 + c];
        }
#pragma unroll
        for (int k = 0; k < 4; k++) {
            int idx = k * 256 + t;
            int r = idx >> 6, c = idx & 63;
            W_s[r][c] = W[(k0 + r) * CC + n0 + c];
        }
        __syncthreads();
#pragma unroll
        for (int kk = 0; kk < 16; kk++) {
            ulonglong2 B = *(const ulonglong2*)&W_s[kk][tcx * 4];
#pragma unroll
            for (int m = 0; m < 4; m++) {
                float av = x_s[trx * 4 + m][kk];
                unsigned long long a2 = pk2(av, av);
                FFMA2(acc2[m][0], a2, B.x);
                FFMA2(acc2[m][1], a2, B.y);
            }
        }
        __syncthreads();
    }
#pragma unroll
    for (int m = 0; m < 4; m++) {
        float4 v;
        upk2(acc2[m][0], v.x, v.y);
        upk2(acc2[m][1], v.z, v.w);
        *(float4*)&g_h[(i0 + trx * 4 + m) * CC + n0 + tcx * 4] = v;
    }
}

// ---------------------------------------------------------------------------
// Kernel 2: el/er dots, then store factored exponentials:
//   g_eL[n,h] = (exp(el), exp(0.2*el)),  g_eR[n,h] = (exp(er), exp(0.2*er))
// exp(leaky_relu(el+er)) == max(eL.x*eR.x, eL.y*eR.y)  (exact identity)
// ---------------------------------------------------------------------------
__global__ void k_elr(const float* __restrict__ a) {
    const int i    = blockIdx.x;
    const int wid  = threadIdx.x >> 5;   // head
    const int lane = threadIdx.x & 31;

    float v1 = g_h[i * CC + wid * FF + lane];
    float v2 = g_h[i * CC + wid * FF + lane + 32];
    float el = v1 * a[lane]      + v2 * a[lane + 32];
    float er = v1 * a[64 + lane] + v2 * a[96 + lane];
#pragma unroll
    for (int off = 16; off > 0; off >>= 1) {
        el += __shfl_xor_sync(0xffffffffu, el, off);
        er += __shfl_xor_sync(0xffffffffu, er, off);
    }
    if (lane == 0) {
        g_eL[i * HH + wid] = make_float2(__expf(el), __expf(NEG_SLOPE * el));
        g_eR[i * HH + wid] = make_float2(__expf(er), __expf(NEG_SLOPE * er));
    }
}

// ---------------------------------------------------------------------------
// Kernel 3: fused masked attention + weighted aggregation (partials).
// Grid: (64 i-tiles, JSPLIT). Block: 256 threads, 8x8 register tile / thread.
// w[i,j,h] = adj[i,j] * max(eL.x[i,h]*eR.x[j,h], eL.y[i,h]*eR.y[j,h])
// ---------------------------------------------------------------------------
__global__ void __launch_bounds__(256) k_attn(const float* __restrict__ adj) {
    extern __shared__ __align__(16) float smem[];
    float*  hs    = smem;                        // [JT][256]   8192 f
    float*  w_s   = smem + 8192;                 // [JT][256]   8192 f
    float*  adj_s = smem + 16384;                // [64][33]    2112 f
    float2* el_s  = (float2*)(smem + 18496);     // [64][4]      256 f2
    float2* er_s  = (float2*)(smem + 19008);     // [JT][4]      128 f2

    const int t  = threadIdx.x;
    const int i0 = blockIdx.x * ITILE;
    const int js = blockIdx.y;
    const int jbase = js * JHALF;

    // mapping for w-phase
    const int h_w = t >> 6;        // 0..3
    const int i_w = t & 63;        // 0..63
    // mapping for GEMM phase
    const int h_g = t >> 6;        // 0..3
    const int tr  = (t >> 3) & 7;  // 0..7 rows
    const int tc  = t & 7;         // 0..7 cols

    el_s[t] = g_eL[i0 * HH + t];   // 256 entries = 64 rows x 4 heads
    __syncthreads();
    const float2 P = el_s[i_w * HH + h_w];

    unsigned long long acc2[8][4];
#pragma unroll
    for (int r = 0; r < 8; r++)
#pragma unroll
        for (int c = 0; c < 4; c++) acc2[r][c] = 0ull;
    float zacc = 0.f;

    for (int jt = 0; jt < JHALF; jt += JT) {
        const int j0 = jbase + jt;
        __syncthreads();   // previous GEMM done, safe to overwrite smem

        // --- load phase ---
#pragma unroll
        for (int k = 0; k < 8; k++) {
            int f4 = k * 256 + t;          // 0..2047
            int jj = f4 >> 6, c4 = f4 & 63;
            *(float4*)&hs[jj * CC + c4 * 4] =
                *(const float4*)&g_h[(j0 + jj) * CC + c4 * 4];
        }
#pragma unroll
        for (int k = 0; k < 8; k++) {
            int idx = k * 256 + t;
            int r = idx >> 5, c = idx & 31;
            adj_s[r * 33 + c] = adj[(size_t)(i0 + r) * NN + j0 + c];
        }
        if (t < JT * HH) er_s[t] = g_eR[j0 * HH + t];
        __syncthreads();

        // --- w phase: thread owns (i_w, h_w), loops over jj (no MUFU!) ---
#pragma unroll 8
        for (int jj = 0; jj < JT; jj++) {
            float2 q = er_s[jj * HH + h_w];
            float w = adj_s[i_w * 33 + jj] * fmaxf(P.x * q.x, P.y * q.y);
            w_s[jj * CC + h_w * 64 + i_w] = w;
            zacc += w;
        }
        __syncthreads();

        // --- GEMM phase: acc[8][8] += w[i][jj] * h[jj][c], packed f32x2 ---
#pragma unroll 2
        for (int jj = 0; jj < JT; jj++) {
            const float* wp = &w_s[jj * CC + h_g * 64 + tr * 8];
            const float* hp = &hs[jj * CC + h_g * 64 + tc * 8];
            float4 w0 = *(const float4*)(wp);
            float4 w1 = *(const float4*)(wp + 4);
            ulonglong2 B0 = *(const ulonglong2*)(hp);
            ulonglong2 B1 = *(const ulonglong2*)(hp + 4);
            float wv[8] = {w0.x, w0.y, w0.z, w0.w, w1.x, w1.y, w1.z, w1.w};
#pragma unroll
            for (int r = 0; r < 8; r++) {
                unsigned long long a2 = pk2(wv[r], wv[r]);
                FFMA2(acc2[r][0], a2, B0.x);
                FFMA2(acc2[r][1], a2, B0.y);
                FFMA2(acc2[r][2], a2, B1.x);
                FFMA2(acc2[r][3], a2, B1.y);
            }
        }
    }

    // --- epilogue: write partials ---
    float* accb = g_acc + (size_t)js * NN * CC;
#pragma unroll
    for (int r = 0; r < 8; r++) {
        int row = i0 + tr * 8 + r;
        float4 v0, v1;
        upk2(acc2[r][0], v0.x, v0.y);
        upk2(acc2[r][1], v0.z, v0.w);
        upk2(acc2[r][2], v1.x, v1.y);
        upk2(acc2[r][3], v1.z, v1.w);
        *(float4*)&accb[(size_t)row * CC + h_g * 64 + tc * 8]     = v0;
        *(float4*)&accb[(size_t)row * CC + h_g * 64 + tc * 8 + 4] = v1;
    }
    g_z[(size_t)js * NN * HH + (i0 + i_w) * HH + h_w] = zacc;
}

// ---------------------------------------------------------------------------
// Kernel 4: finalize out[i][f] = (1/H) * sum_h (acc0+acc1)[i][h*64+f]/(z0+z1)[i][h]
// ---------------------------------------------------------------------------
__global__ void k_finalize(float* __restrict__ out) {
    int idx = blockIdx.x * blockDim.x + threadIdx.x;   // 0 .. N*FF-1
    int i = idx >> 6, f = idx & 63;
    float sum = 0.f;
#pragma unroll
    for (int h = 0; h < HH; h++) {
        float A = g_acc[(size_t)i * CC + h * 64 + f] +
                  g_acc[(size_t)NN * CC + (size_t)i * CC + h * 64 + f];
        float Z = g_z[i * HH + h] + g_z[NN * HH + i * HH + h];
        sum += A / Z;
    }
    out[idx] = 0.25f * sum;
}

// ---------------------------------------------------------------------------
extern "C" void kernel_launch(void* const* d_in, const int* in_sizes, int n_in,
                              void* d_out, int out_size) {
    const float* x   = (const float*)d_in[0];
    const float* adj = (const float*)d_in[1];
    const float* W   = (const float*)d_in[2];
    const float* a   = (const float*)d_in[3];
    float* out = (float*)d_out;

    const int attn_smem = 19264 * 4;   // 8192+8192+2112+512+256 floats
    cudaFuncSetAttribute(k_attn, cudaFuncAttributeMaxDynamicSharedMemorySize,
                         attn_smem);

    k_gemm_xw<<<dim3(NN / 64, CC / 64), 256>>>(x, W);
    k_elr<<<NN, 128>>>(a);
    k_attn<<<dim3(NN / ITILE, JSPLIT), 256, attn_smem>>>(adj);
    k_finalize<<<(NN * FF) / 256, 256>>>(out);
}

// round 5
// speedup vs baseline: 3.0995x; 2.5704x over previous
#include <cuda_runtime.h>
#include <cuda_bf16.h>
#include <cstdint>

// Problem constants
#define NN    4096
#define INF_  256
#define FF    64
#define HH    4
#define CC    256      // HH*FF
#define NEG_SLOPE 0.2f

// Attention tiling
#define JS      4
#define JRANGE  (NN / JS)         // 1024
#define JT      32
#define NTILES  (JRANGE / JT)     // 32
#define ITM     128

#define HS_PITCH  264             // floats; bank = (8j + c) & 31 -> conflict-free frags
#define ADJ_PITCH 36              // floats; bank = (4i + j) & 31 -> conflict-free frags
#define OFF_HS    0
#define OFF_ADJ   (JT * HS_PITCH)                 // 8448
#define OFF_ER    (OFF_ADJ + ITM * ADJ_PITCH)     // 8448 + 4608 = 13056
#define ATTN_SMEM ((OFF_ER + 256) * 4)            // 53248 B

// Scratch (device globals: allocation-free rule)
__device__ float  g_h[NN * CC];            // 4 MB
__device__ float2 g_eL[NN * HH];           // (exp(el), exp(0.2*el))
__device__ float2 g_eR[NN * HH];
__device__ float  g_acc[JS * NN * CC];     // 16 MB partial numerators
__device__ float  g_z[JS * NN * HH];

// ---- packed f32x2 helpers (gemm1) ----
__device__ __forceinline__ unsigned long long pk2(float lo, float hi) {
    unsigned long long r;
    asm("mov.b64 %0, {%1, %2};" : "=l"(r) : "f"(lo), "f"(hi));
    return r;
}
__device__ __forceinline__ void upk2(unsigned long long v, float& lo, float& hi) {
    asm("mov.b64 {%0, %1}, %2;" : "=f"(lo), "=f"(hi) : "l"(v));
}
#define FFMA2(d, a, b) \
    asm("fma.rn.f32x2 %0, %1, %2, %0;" : "+l"(d) : "l"(a), "l"(b))

// ---- tf32 mma helpers ----
__device__ __forceinline__ uint32_t to_tf32(float f) {
    uint32_t r;
    asm("cvt.rna.tf32.f32 %0, %1;" : "=r"(r) : "f"(f));
    return r;
}
__device__ __forceinline__ void mma_tf32(float* d, uint32_t a0, uint32_t a1,
                                         uint32_t a2, uint32_t a3,
                                         uint32_t b0, uint32_t b1) {
    asm volatile(
        "mma.sync.aligned.m16n8k8.row.col.f32.tf32.tf32.f32 "
        "{%0,%1,%2,%3}, {%4,%5,%6,%7}, {%8,%9}, {%0,%1,%2,%3};"
        : "+f"(d[0]), "+f"(d[1]), "+f"(d[2]), "+f"(d[3])
        : "r"(a0), "r"(a1), "r"(a2), "r"(a3), "r"(b0), "r"(b1));
}

// ---------------------------------------------------------------------------
// Kernel 1: h = x @ W   (fp32, packed f32x2)
// ---------------------------------------------------------------------------
__global__ void k_gemm_xw(const float* __restrict__ x,
                          const float* __restrict__ W) {
    __shared__ float x_s[64][17];
    __shared__ __align__(16) float W_s[16][64];

    const int t  = threadIdx.x;
    const int i0 = blockIdx.x * 64;
    const int n0 = blockIdx.y * 64;
    const int tcx = t & 15;
    const int trx = t >> 4;

    unsigned long long acc2[4][2];
#pragma unroll
    for (int m = 0; m < 4; m++) { acc2[m][0] = 0ull; acc2[m][1] = 0ull; }

    for (int k0 = 0; k0 < INF_; k0 += 16) {
#pragma unroll
        for (int k = 0; k < 4; k++) {
            int idx = k * 256 + t;
            x_s[idx >> 4][idx & 15] = x[(i0 + (idx >> 4)) * INF_ + k0 + (idx & 15)];
        }
#pragma unroll
        for (int k = 0; k < 4; k++) {
            int idx = k * 256 + t;
            W_s[idx >> 6][idx & 63] = W[(k0 + (idx >> 6)) * CC + n0 + (idx & 63)];
        }
        __syncthreads();
#pragma unroll
        for (int kk = 0; kk < 16; kk++) {
            ulonglong2 B = *(const ulonglong2*)&W_s[kk][tcx * 4];
#pragma unroll
            for (int m = 0; m < 4; m++) {
                float av = x_s[trx * 4 + m][kk];
                unsigned long long a2 = pk2(av, av);
                FFMA2(acc2[m][0], a2, B.x);
                FFMA2(acc2[m][1], a2, B.y);
            }
        }
        __syncthreads();
    }
#pragma unroll
    for (int m = 0; m < 4; m++) {
        float4 v;
        upk2(acc2[m][0], v.x, v.y);
        upk2(acc2[m][1], v.z, v.w);
        *(float4*)&g_h[(i0 + trx * 4 + m) * CC + n0 + tcx * 4] = v;
    }
}

// ---------------------------------------------------------------------------
// Kernel 2: el/er dots -> factored exponentials
// exp(leaky_relu(el+er)) == max(eL.x*eR.x, eL.y*eR.y)
// ---------------------------------------------------------------------------
__global__ void k_elr(const float* __restrict__ a) {
    const int i    = blockIdx.x;
    const int wid  = threadIdx.x >> 5;
    const int lane = threadIdx.x & 31;

    float v1 = g_h[i * CC + wid * FF + lane];
    float v2 = g_h[i * CC + wid * FF + lane + 32];
    float el = v1 * a[lane]      + v2 * a[lane + 32];
    float er = v1 * a[64 + lane] + v2 * a[96 + lane];
#pragma unroll
    for (int off = 16; off > 0; off >>= 1) {
        el += __shfl_xor_sync(0xffffffffu, el, off);
        er += __shfl_xor_sync(0xffffffffu, er, off);
    }
    if (lane == 0) {
        g_eL[i * HH + wid] = make_float2(__expf(el), __expf(NEG_SLOPE * el));
        g_eR[i * HH + wid] = make_float2(__expf(er), __expf(NEG_SLOPE * er));
    }
}

// ---------------------------------------------------------------------------
// Kernel 3: fused attention via mma.sync tf32.
// Grid (32 i-tiles, JS). 512 thr = 16 warps: warp (hh = wid>>2, wm = wid&3)
// owns rows [wm*32, wm*32+32) of head hh. w computed straight into A frags.
// ---------------------------------------------------------------------------
__global__ void __launch_bounds__(512, 1) k_attn(const float* __restrict__ adj) {
    extern __shared__ __align__(16) float sm[];
    float*  hs   = sm + OFF_HS;    // [JT][HS_PITCH]
    float*  adjs = sm + OFF_ADJ;   // [ITM][ADJ_PITCH]
    float2* ers  = (float2*)(sm + OFF_ER);   // [JT*HH]

    const int tid  = threadIdx.x;
    const int wid  = tid >> 5;
    const int lane = tid & 31;
    const int hh   = wid >> 2;
    const int wm   = wid & 3;
    const int m0   = wm * 32;
    const int gid  = lane >> 2;    // 0..7
    const int tig  = lane & 3;     // 0..3
    const int i0   = blockIdx.x * ITM;
    const int js   = blockIdx.y;
    const int jbase = js * JRANGE;
    const int cbase = hh * 64 + gid;

    // row exp-factors pinned in registers: rows i0+m0+16m+8ri+gid
    float2 P[4];
#pragma unroll
    for (int m = 0; m < 2; m++)
#pragma unroll
        for (int ri = 0; ri < 2; ri++)
            P[m * 2 + ri] = g_eL[(i0 + m0 + 16 * m + 8 * ri + gid) * HH + hh];

    float acc[2][8][4];
#pragma unroll
    for (int m = 0; m < 2; m++)
#pragma unroll
        for (int n = 0; n < 8; n++)
#pragma unroll
            for (int q = 0; q < 4; q++) acc[m][n][q] = 0.f;
    float z[4] = {0.f, 0.f, 0.f, 0.f};

    for (int t = 0; t < NTILES; t++) {
        const int j0 = jbase + t * JT;
        __syncthreads();   // previous tile's reads done

        // ---- stage hs: 32 x 256 floats ----
#pragma unroll
        for (int q = 0; q < 4; q++) {
            int idx = q * 512 + tid;           // 0..2047 float4s
            int jj = idx >> 6, c4 = (idx & 63) * 4;
            *(float4*)&hs[jj * HS_PITCH + c4] =
                *(const float4*)&g_h[(size_t)(j0 + jj) * CC + c4];
        }
        // ---- stage adj: 128 x 32 ----
#pragma unroll
        for (int q = 0; q < 2; q++) {
            int idx = q * 512 + tid;           // 0..1023 float4s
            int r = idx >> 3, c4 = (idx & 7) * 4;
            float4 v = *(const float4*)&adj[(size_t)(i0 + r) * NN + j0 + c4];
            adjs[r * ADJ_PITCH + c4 + 0] = v.x;
            adjs[r * ADJ_PITCH + c4 + 1] = v.y;
            adjs[r * ADJ_PITCH + c4 + 2] = v.z;
            adjs[r * ADJ_PITCH + c4 + 3] = v.w;
        }
        // ---- stage er: 32 x 4 float2 (contiguous) ----
        if (tid < JT * HH) ers[tid] = g_eR[(size_t)j0 * HH + tid];
        __syncthreads();

#pragma unroll
        for (int k = 0; k < 4; k++) {
            const int jA = k * 8 + tig;
            const float2 Q0 = ers[jA * HH + hh];
            const float2 Q1 = ers[(jA + 4) * HH + hh];

            // B fragments (conflict-free: bank = 8*(lane%4) + (lane>>2))
            uint32_t b0[8], b1[8];
            const float* hr0 = hs + jA * HS_PITCH + cbase;
            const float* hr1 = hs + (jA + 4) * HS_PITCH + cbase;
#pragma unroll
            for (int n = 0; n < 8; n++) {
                b0[n] = to_tf32(hr0[n * 8]);
                b1[n] = to_tf32(hr1[n * 8]);
            }

#pragma unroll
            for (int m = 0; m < 2; m++) {
                const int ib = m0 + 16 * m + gid;
                float w00 = adjs[ib * ADJ_PITCH + jA] *
                            fmaxf(P[2 * m].x * Q0.x, P[2 * m].y * Q0.y);
                float w10 = adjs[(ib + 8) * ADJ_PITCH + jA] *
                            fmaxf(P[2 * m + 1].x * Q0.x, P[2 * m + 1].y * Q0.y);
                float w01 = adjs[ib * ADJ_PITCH + jA + 4] *
                            fmaxf(P[2 * m].x * Q1.x, P[2 * m].y * Q1.y);
                float w11 = adjs[(ib + 8) * ADJ_PITCH + jA + 4] *
                            fmaxf(P[2 * m + 1].x * Q1.x, P[2 * m + 1].y * Q1.y);
                z[2 * m]     += w00 + w01;
                z[2 * m + 1] += w10 + w11;
                uint32_t a0 = to_tf32(w00), a1 = to_tf32(w10);
                uint32_t a2 = to_tf32(w01), a3 = to_tf32(w11);
#pragma unroll
                for (int n = 0; n < 8; n++)
                    mma_tf32(acc[m][n], a0, a1, a2, a3, b0[n], b1[n]);
            }
        }
    }

    // ---- z reduce across tig lanes (quad) ----
#pragma unroll
    for (int q = 0; q < 4; q++) {
        z[q] += __shfl_xor_sync(0xffffffffu, z[q], 1);
        z[q] += __shfl_xor_sync(0xffffffffu, z[q], 2);
    }
    if (tig == 0) {
#pragma unroll
        for (int m = 0; m < 2; m++)
#pragma unroll
            for (int ri = 0; ri < 2; ri++) {
                int row = i0 + m0 + 16 * m + 8 * ri + gid;
                g_z[(size_t)js * NN * HH + row * HH + hh] = z[2 * m + ri];
            }
    }

    // ---- accumulator store ----
    float* accb = g_acc + (size_t)js * NN * CC;
#pragma unroll
    for (int m = 0; m < 2; m++) {
        int row0 = i0 + m0 + 16 * m + gid;
#pragma unroll
        for (int n = 0; n < 8; n++) {
            int col = hh * 64 + n * 8 + tig * 2;
            *(float2*)&accb[(size_t)row0 * CC + col] =
                make_float2(acc[m][n][0], acc[m][n][1]);
            *(float2*)&accb[(size_t)(row0 + 8) * CC + col] =
                make_float2(acc[m][n][2], acc[m][n][3]);
        }
    }
}

// ---------------------------------------------------------------------------
// Kernel 4: finalize. out[i][f] = 0.25 * sum_h (sum_js A)/(sum_js Z)
// ---------------------------------------------------------------------------
__global__ void k_finalize(float* __restrict__ out) {
    int idx = blockIdx.x * blockDim.x + threadIdx.x;   // 0 .. N*16-1
    int i = idx >> 4, f4 = (idx & 15) * 4;
    float4 s = make_float4(0.f, 0.f, 0.f, 0.f);
#pragma unroll
    for (int h = 0; h < HH; h++) {
        float4 A = make_float4(0.f, 0.f, 0.f, 0.f);
        float  Z = 0.f;
#pragma unroll
        for (int js = 0; js < JS; js++) {
            float4 v = *(const float4*)&g_acc[((size_t)js * NN + i) * CC + h * 64 + f4];
            A.x += v.x; A.y += v.y; A.z += v.z; A.w += v.w;
            Z += g_z[(size_t)js * NN * HH + i * HH + h];
        }
        float r = 1.f / Z;
        s.x += A.x * r; s.y += A.y * r; s.z += A.z * r; s.w += A.w * r;
    }
    *(float4*)&out[i * FF + f4] =
        make_float4(0.25f * s.x, 0.25f * s.y, 0.25f * s.z, 0.25f * s.w);
}

// ---------------------------------------------------------------------------
extern "C" void kernel_launch(void* const* d_in, const int* in_sizes, int n_in,
                              void* d_out, int out_size) {
    const float* x   = (const float*)d_in[0];
    const float* adj = (const float*)d_in[1];
    const float* W   = (const float*)d_in[2];
    const float* a   = (const float*)d_in[3];
    float* out = (float*)d_out;

    cudaFuncSetAttribute(k_attn, cudaFuncAttributeMaxDynamicSharedMemorySize,
                         ATTN_SMEM);

    k_gemm_xw<<<dim3(NN / 64, CC / 64), 256>>>(x, W);
    k_elr<<<NN, 128>>>(a);
    k_attn<<<dim3(NN / ITM, JS), 512, ATTN_SMEM>>>(adj);
    k_finalize<<<(NN * 16) / 256, 256>>>(out);
}

// round 7
// speedup vs baseline: 4.0414x; 1.3039x over previous
#include <cuda_runtime.h>
#include <cuda_bf16.h>
#include <cstdint>

// Problem constants
#define NN    4096
#define INF_  256
#define FF    64
#define HH    4
#define CC    256      // HH*FF
#define NEG_SLOPE 0.2f

// Attention tiling
#define JS      4
#define JRANGE  (NN / JS)         // 1024
#define JT      32
#define NTILES  (JRANGE / JT)     // 32
#define ITM     128

#define HS_PITCH  264             // floats; conflict-free fragment reads
#define ADJ_PITCH 36
#define HS_BUF    (JT * HS_PITCH)        // 8448 floats per buffer
#define ADJ_BUF   (ITM * ADJ_PITCH)      // 4608
#define ER_BUF    (JT * HH * 2)          // 256 floats (128 float2)
#define OFF_HS    0
#define OFF_ADJ   (2 * HS_BUF)                    // 16896
#define OFF_ER    (OFF_ADJ + 2 * ADJ_BUF)         // 26112
#define ATTN_SMEM ((OFF_ER + 2 * ER_BUF) * 4)     // 106496 B

// Scratch (device globals: allocation-free rule)
__device__ float  g_h[NN * CC];            // 4 MB
__device__ float2 g_eL[NN * HH];           // (exp(el), exp(0.2*el))
__device__ float2 g_eR[NN * HH];
__device__ float  g_acc[JS * NN * CC];     // 16 MB partial numerators
__device__ float  g_z[JS * NN * HH];

// ---- packed f32x2 helpers (gemm1) ----
__device__ __forceinline__ unsigned long long pk2(float lo, float hi) {
    unsigned long long r;
    asm("mov.b64 %0, {%1, %2};" : "=l"(r) : "f"(lo), "f"(hi));
    return r;
}
__device__ __forceinline__ void upk2(unsigned long long v, float& lo, float& hi) {
    asm("mov.b64 {%0, %1}, %2;" : "=f"(lo), "=f"(hi) : "l"(v));
}
#define FFMA2(d, a, b) \
    asm("fma.rn.f32x2 %0, %1, %2, %0;" : "+l"(d) : "l"(a), "l"(b))

// ---- tf32 mma (raw fp32 bits: HW truncates to 19 bits) ----
__device__ __forceinline__ void mma_tf32(float* d, uint32_t a0, uint32_t a1,
                                         uint32_t a2, uint32_t a3,
                                         uint32_t b0, uint32_t b1) {
    asm volatile(
        "mma.sync.aligned.m16n8k8.row.col.f32.tf32.tf32.f32 "
        "{%0,%1,%2,%3}, {%4,%5,%6,%7}, {%8,%9}, {%0,%1,%2,%3};"
        : "+f"(d[0]), "+f"(d[1]), "+f"(d[2]), "+f"(d[3])
        : "r"(a0), "r"(a1), "r"(a2), "r"(a3), "r"(b0), "r"(b1));
}

// ---- cp.async ----
__device__ __forceinline__ uint32_t smem_u32(const void* p) {
    uint32_t a;
    asm("{ .reg .u64 t; cvta.to.shared.u64 t, %1; cvt.u32.u64 %0, t; }"
        : "=r"(a) : "l"(p));
    return a;
}
#define CP16(dst, src) \
    asm volatile("cp.async.cg.shared.global [%0], [%1], 16;" \
                 :: "r"(dst), "l"(src) : "memory")
#define CP_COMMIT() asm volatile("cp.async.commit_group;" ::: "memory")
#define CP_WAIT0()  asm volatile("cp.async.wait_group 0;" ::: "memory")

// ---------------------------------------------------------------------------
// Kernel 1: h = x @ W   (fp32, packed f32x2)
// ---------------------------------------------------------------------------
__global__ void k_gemm_xw(const float* __restrict__ x,
                          const float* __restrict__ W) {
    __shared__ float x_s[64][17];
    __shared__ __align__(16) float W_s[16][64];

    const int t  = threadIdx.x;
    const int i0 = blockIdx.x * 64;
    const int n0 = blockIdx.y * 64;
    const int tcx = t & 15;
    const int trx = t >> 4;

    unsigned long long acc2[4][2];
#pragma unroll
    for (int m = 0; m < 4; m++) { acc2[m][0] = 0ull; acc2[m][1] = 0ull; }

    for (int k0 = 0; k0 < INF_; k0 += 16) {
#pragma unroll
        for (int k = 0; k < 4; k++) {
            int idx = k * 256 + t;
            x_s[idx >> 4][idx & 15] = x[(i0 + (idx >> 4)) * INF_ + k0 + (idx & 15)];
        }
#pragma unroll
        for (int k = 0; k < 4; k++) {
            int idx = k * 256 + t;
            W_s[idx >> 6][idx & 63] = W[(k0 + (idx >> 6)) * CC + n0 + (idx & 63)];
        }
        __syncthreads();
#pragma unroll
        for (int kk = 0; kk < 16; kk++) {
            ulonglong2 B = *(const ulonglong2*)&W_s[kk][tcx * 4];
#pragma unroll
            for (int m = 0; m < 4; m++) {
                float av = x_s[trx * 4 + m][kk];
                unsigned long long a2 = pk2(av, av);
                FFMA2(acc2[m][0], a2, B.x);
                FFMA2(acc2[m][1], a2, B.y);
            }
        }
        __syncthreads();
    }
#pragma unroll
    for (int m = 0; m < 4; m++) {
        float4 v;
        upk2(acc2[m][0], v.x, v.y);
        upk2(acc2[m][1], v.z, v.w);
        *(float4*)&g_h[(i0 + trx * 4 + m) * CC + n0 + tcx * 4] = v;
    }
}

// ---------------------------------------------------------------------------
// Kernel 2: el/er dots -> factored exponentials
// ---------------------------------------------------------------------------
__global__ void k_elr(const float* __restrict__ a) {
    const int i    = blockIdx.x;
    const int wid  = threadIdx.x >> 5;
    const int lane = threadIdx.x & 31;

    float v1 = g_h[i * CC + wid * FF + lane];
    float v2 = g_h[i * CC + wid * FF + lane + 32];
    float el = v1 * a[lane]      + v2 * a[lane + 32];
    float er = v1 * a[64 + lane] + v2 * a[96 + lane];
#pragma unroll
    for (int off = 16; off > 0; off >>= 1) {
        el += __shfl_xor_sync(0xffffffffu, el, off);
        er += __shfl_xor_sync(0xffffffffu, er, off);
    }
    if (lane == 0) {
        g_eL[i * HH + wid] = make_float2(__expf(el), __expf(NEG_SLOPE * el));
        g_eR[i * HH + wid] = make_float2(__expf(er), __expf(NEG_SLOPE * er));
    }
}

// ---------------------------------------------------------------------------
// Kernel 3: fused attention via mma.sync tf32, cp.async double-buffered.
// ---------------------------------------------------------------------------
__global__ void __launch_bounds__(512, 1) k_attn(const float* __restrict__ adj) {
    extern __shared__ __align__(16) float sm[];
    const uint32_t sm_b = smem_u32(sm);

    const int tid  = threadIdx.x;
    const int wid  = tid >> 5;
    const int lane = tid & 31;
    const int hh   = wid >> 2;
    const int wm   = wid & 3;
    const int m0   = wm * 32;
    const int gid  = lane >> 2;    // 0..7
    const int tig  = lane & 3;     // 0..3
    const int i0   = blockIdx.x * ITM;
    const int js   = blockIdx.y;
    const int jbase = js * JRANGE;
    const int cbase = hh * 64 + gid;

    // staging indices
    const int hjj[4] = { (0 * 512 + tid) >> 6, (1 * 512 + tid) >> 6,
                         (2 * 512 + tid) >> 6, (3 * 512 + tid) >> 6 };
    const int hc4[4] = { ((0 * 512 + tid) & 63) * 4, ((1 * 512 + tid) & 63) * 4,
                         ((2 * 512 + tid) & 63) * 4, ((3 * 512 + tid) & 63) * 4 };
    const int ar[2]  = { (0 * 512 + tid) >> 3, (1 * 512 + tid) >> 3 };
    const int ac4[2] = { ((0 * 512 + tid) & 7) * 4, ((1 * 512 + tid) & 7) * 4 };

    // row exp-factors pinned in registers
    float2 P[4];
#pragma unroll
    for (int m = 0; m < 2; m++)
#pragma unroll
        for (int ri = 0; ri < 2; ri++)
            P[m * 2 + ri] = g_eL[(i0 + m0 + 16 * m + 8 * ri + gid) * HH + hh];

    float acc[2][8][4];
#pragma unroll
    for (int m = 0; m < 2; m++)
#pragma unroll
        for (int n = 0; n < 8; n++)
#pragma unroll
            for (int q = 0; q < 4; q++) acc[m][n][q] = 0.f;
    float z[4] = {0.f, 0.f, 0.f, 0.f};

    // ---- issue staging for tile t into buffer b ----
    auto issue = [&](int t, int b) {
        const int j0 = jbase + t * JT;
        const uint32_t hsb  = sm_b + (OFF_HS  + b * HS_BUF)  * 4;
        const uint32_t adjb = sm_b + (OFF_ADJ + b * ADJ_BUF) * 4;
        const uint32_t erb  = sm_b + (OFF_ER  + b * ER_BUF)  * 4;
#pragma unroll
        for (int q = 0; q < 4; q++)
            CP16(hsb + (hjj[q] * HS_PITCH + hc4[q]) * 4,
                 (const char*)&g_h[(size_t)(j0 + hjj[q]) * CC + hc4[q]]);
#pragma unroll
        for (int q = 0; q < 2; q++)
            CP16(adjb + (ar[q] * ADJ_PITCH + ac4[q]) * 4,
                 (const char*)&adj[(size_t)(i0 + ar[q]) * NN + j0 + ac4[q]]);
        if (tid < 64)
            CP16(erb + tid * 16, (const char*)&g_eR[j0 * HH] + tid * 16);
        CP_COMMIT();
    };

    issue(0, 0);

    for (int t = 0; t < NTILES; t++) {
        const int b = t & 1;
        CP_WAIT0();
        __syncthreads();               // tile t visible; tile t-1 compute done
        if (t + 1 < NTILES) issue(t + 1, b ^ 1);

        const float*  hs   = sm + OFF_HS  + b * HS_BUF;
        const float*  adjs = sm + OFF_ADJ + b * ADJ_BUF;
        const float2* ers  = (const float2*)(sm + OFF_ER + b * ER_BUF);

#pragma unroll
        for (int k = 0; k < 4; k++) {
            const int jA = k * 8 + tig;
            const float2 Q0 = ers[jA * HH + hh];
            const float2 Q1 = ers[(jA + 4) * HH + hh];

            uint32_t b0[8], b1[8];
            const float* hr0 = hs + jA * HS_PITCH + cbase;
            const float* hr1 = hs + (jA + 4) * HS_PITCH + cbase;
#pragma unroll
            for (int n = 0; n < 8; n++) {
                b0[n] = __float_as_uint(hr0[n * 8]);
                b1[n] = __float_as_uint(hr1[n * 8]);
            }

#pragma unroll
            for (int m = 0; m < 2; m++) {
                const int ib = m0 + 16 * m + gid;
                float w00 = adjs[ib * ADJ_PITCH + jA] *
                            fmaxf(P[2 * m].x * Q0.x, P[2 * m].y * Q0.y);
                float w10 = adjs[(ib + 8) * ADJ_PITCH + jA] *
                            fmaxf(P[2 * m + 1].x * Q0.x, P[2 * m + 1].y * Q0.y);
                float w01 = adjs[ib * ADJ_PITCH + jA + 4] *
                            fmaxf(P[2 * m].x * Q1.x, P[2 * m].y * Q1.y);
                float w11 = adjs[(ib + 8) * ADJ_PITCH + jA + 4] *
                            fmaxf(P[2 * m + 1].x * Q1.x, P[2 * m + 1].y * Q1.y);
                z[2 * m]     += w00 + w01;
                z[2 * m + 1] += w10 + w11;
                uint32_t a0 = __float_as_uint(w00), a1 = __float_as_uint(w10);
                uint32_t a2 = __float_as_uint(w01), a3 = __float_as_uint(w11);
#pragma unroll
                for (int n = 0; n < 8; n++)
                    mma_tf32(acc[m][n], a0, a1, a2, a3, b0[n], b1[n]);
            }
        }
    }

    // ---- z reduce across quad lanes ----
#pragma unroll
    for (int q = 0; q < 4; q++) {
        z[q] += __shfl_xor_sync(0xffffffffu, z[q], 1);
        z[q] += __shfl_xor_sync(0xffffffffu, z[q], 2);
    }
    if (tig == 0) {
#pragma unroll
        for (int m = 0; m < 2; m++)
#pragma unroll
            for (int ri = 0; ri < 2; ri++) {
                int row = i0 + m0 + 16 * m + 8 * ri + gid;
                g_z[(size_t)js * NN * HH + row * HH + hh] = z[2 * m + ri];
            }
    }

    // ---- accumulator store ----
    float* accb = g_acc + (size_t)js * NN * CC;
#pragma unroll
    for (int m = 0; m < 2; m++) {
        int row0 = i0 + m0 + 16 * m + gid;
#pragma unroll
        for (int n = 0; n < 8; n++) {
            int col = hh * 64 + n * 8 + tig * 2;
            *(float2*)&accb[(size_t)row0 * CC + col] =
                make_float2(acc[m][n][0], acc[m][n][1]);
            *(float2*)&accb[(size_t)(row0 + 8) * CC + col] =
                make_float2(acc[m][n][2], acc[m][n][3]);
        }
    }
}

// ---------------------------------------------------------------------------
// Kernel 4: finalize, 2 threads per output (h-split), shfl combine.
// ---------------------------------------------------------------------------
__global__ void k_finalize(float* __restrict__ out) {
    int idx = blockIdx.x * blockDim.x + threadIdx.x;   // 0 .. N*32-1
    int half = idx & 1;
    int o = idx >> 1;                  // 0 .. N*16-1
    int i = o >> 4, f4 = (o & 15) * 4;

    float4 s = make_float4(0.f, 0.f, 0.f, 0.f);
#pragma unroll
    for (int hq = 0; hq < 2; hq++) {
        int h = half * 2 + hq;
        float4 A = make_float4(0.f, 0.f, 0.f, 0.f);
        float  Z = 0.f;
#pragma unroll
        for (int js = 0; js < JS; js++) {
            float4 v = *(const float4*)&g_acc[((size_t)js * NN + i) * CC + h * 64 + f4];
            A.x += v.x; A.y += v.y; A.z += v.z; A.w += v.w;
            Z += g_z[(size_t)js * NN * HH + i * HH + h];
        }
        float r = 1.f / Z;
        s.x += A.x * r; s.y += A.y * r; s.z += A.z * r; s.w += A.w * r;
    }
    s.x += __shfl_xor_sync(0xffffffffu, s.x, 1);
    s.y += __shfl_xor_sync(0xffffffffu, s.y, 1);
    s.z += __shfl_xor_sync(0xffffffffu, s.z, 1);
    s.w += __shfl_xor_sync(0xffffffffu, s.w, 1);
    if (half == 0)
        *(float4*)&out[i * FF + f4] =
            make_float4(0.25f * s.x, 0.25f * s.y, 0.25f * s.z, 0.25f * s.w);
}

// ---------------------------------------------------------------------------
extern "C" void kernel_launch(void* const* d_in, const int* in_sizes, int n_in,
                              void* d_out, int out_size) {
    const float* x   = (const float*)d_in[0];
    const float* adj = (const float*)d_in[1];
    const float* W   = (const float*)d_in[2];
    const float* a   = (const float*)d_in[3];
    float* out = (float*)d_out;

    cudaFuncSetAttribute(k_attn, cudaFuncAttributeMaxDynamicSharedMemorySize,
                         ATTN_SMEM);

    k_gemm_xw<<<dim3(NN / 64, CC / 64), 256>>>(x, W);
    k_elr<<<NN, 128>>>(a);
    k_attn<<<dim3(NN / ITM, JS), 512, ATTN_SMEM>>>(adj);
    k_finalize<<<(NN * 32) / 512, 512>>>(out);
}